// round 15
// baseline (speedup 1.0000x reference)
#include <cuda_runtime.h>
#include <cuda_bf16.h>

static constexpr int BATCH = 2048;
static constexpr int NSLOT = 64;
static constexpr int FEAT  = 19;
static constexpr int ROWF  = NSLOT * FEAT;       // 1216 floats per tensor/batch
static constexpr int VEC4  = ROWF / 4;           // 304 float4
static constexpr int WPC   = 4;                  // warps (=batches) per CTA
static constexpr int TPB   = 32 * WPC;           // 128
static constexpr int GRID  = BATCH / WPC;        // 512

__device__ float g_blockpart[GRID];
__device__ int   g_count = 0;                    // self-resetting, replay-safe

using ull = unsigned long long;

// Replicated-register 64-bit OR across the warp (2x hardware redux).
__device__ __forceinline__ ull warp_or64(ull v) {
    const unsigned lo = __reduce_or_sync(0xffffffffu, (unsigned)v);
    const unsigned hi = __reduce_or_sync(0xffffffffu, (unsigned)(v >> 32));
    return ((ull)hi << 32) | (ull)lo;
}

// One WARP per batch. Sorted nearest-free-neighbor matching. Loop state in
// registers (R11-validated); lane l owns SORTED POSITIONS {l, l+32} for the
// mailbox/accept so the free-mask update is 2 ballots instead of 2 REDUX.
__global__ __launch_bounds__(TPB) void spotting_kernel(
    const float* __restrict__ y_true,
    const float* __restrict__ y_pred,
    float*       __restrict__ out)
{
    const unsigned FULL = 0xffffffffu;
    const int w = threadIdx.x >> 5;
    const int l = threadIdx.x & 31;
    const int b = blockIdx.x * WPC + w;

    __shared__ alignas(16) float s_yt[WPC][ROWF];
    __shared__ alignas(16) float s_yp[WPC][ROWF];
    __shared__ ull   s_ck[WPC][NSLOT];    // setup: unsorted keys; then mailbox BY POSITION
    __shared__ ull   s_key[WPC][NSLOT];   // sorted (p_bits<<6)|j
    __shared__ int   s_perm[WPC][NSLOT];  // row -> column
    __shared__ float s_wpart[WPC];
    __shared__ int   s_flag;

    // ---- coalesced stage of this batch (10 x LDG.128 per lane/tensor) ----
    {
        const float4* gt = reinterpret_cast<const float4*>(y_true + (size_t)b * ROWF);
        const float4* gp = reinterpret_cast<const float4*>(y_pred + (size_t)b * ROWF);
        float4* dt = reinterpret_cast<float4*>(s_yt[w]);
        float4* dp = reinterpret_cast<float4*>(s_yp[w]);
        #pragma unroll
        for (int k = l; k < VEC4; k += 32) { dt[k] = gt[k]; dp[k] = gp[k]; }
    }
    __syncwarp();

    const int r0 = l, r1 = l + 32;
    const float a0 = s_yt[w][r0 * FEAT + 0];
    const float x0 = s_yt[w][r0 * FEAT + 1];
    const float a1 = s_yt[w][r1 * FEAT + 0];
    const float x1 = s_yt[w][r1 * FEAT + 1];

    // ---- setup: keys, rank-sort ----
    s_ck[w][r0]   = ((ull)__float_as_uint(s_yp[w][r0 * FEAT + 1]) << 6) | (ull)r0;
    s_ck[w][r1]   = ((ull)__float_as_uint(s_yp[w][r1 * FEAT + 1]) << 6) | (ull)r1;
    s_perm[w][r0] = r0;                    // defensive (always overwritten)
    s_perm[w][r1] = r1;
    __syncwarp();
    #pragma unroll
    for (int s = 0; s < 2; ++s) {
        const int c = s ? r1 : r0;
        const ull mykey = s_ck[w][c];
        int rank = 0;
        #pragma unroll 8
        for (int j = 0; j < NSLOT; ++j) rank += (s_ck[w][j] < mykey);
        s_key[w][rank] = mykey;            // unique keys -> perfect scatter
    }
    __syncwarp();
    s_ck[w][r0] = 0ULL;                    // mailbox (indexed by sorted pos)
    s_ck[w][r1] = 0ULL;
    // Lane's OWNED sorted positions l, l+32 -> their column ids (registers).
    const int jown_lo = (int)(s_key[w][l]      & 63ULL);
    const int jown_hi = (int)(s_key[w][l + 32] & 63ULL);
    __syncwarp();

    // Binary search: pos = #\{p < x\} over sorted keys (p bits monotone).
    auto lower_pos = [&](float x) -> int {
        const unsigned xb = __float_as_uint(x);
        int pos = 0;
        #pragma unroll
        for (int s = 32; s; s >>= 1) {
            const unsigned pb = (unsigned)(s_key[w][pos + s - 1] >> 6);
            if (pb < xb) pos += s;
        }
        return pos;
    };
    const int pos0 = lower_pos(x0);
    const int pos1 = lower_pos(x1);
    const ull lowm0 = (pos0 >= 64) ? ~0ULL : ((1ULL << pos0) - 1ULL);
    const ull lowm1 = (pos1 >= 64) ? ~0ULL : ((1ULL << pos1) - 1ULL);

    // Propose: best over <=4 nearest-free candidates; select by (d desc,
    // j asc) == jnp.argmax ties; returns packed mailbox value + position.
    auto propose_eval = [&](float x, ull lowm, ull freem, ull& val, int& bpos) {
        ull best = 0ULL; int bp = 0;
        auto consider = [&](int c) {
            const ull   key = s_key[w][c];
            const float p   = __uint_as_float((unsigned)(key >> 6));
            const int   j   = (int)(key & 63ULL);
            const float d   = 1.0f - fabsf(x - p);
            const ull   sk  = ((ull)__float_as_uint(d) << 6) | (ull)(63 - j);
            if (sk > best) { best = sk; bp = c; }
        };
        ull below = freem & lowm;
        ull above = freem & ~lowm;
        if (below) {                        // 2 nearest free below
            int c = 63 - __clzll((long long)below);
            below &= ~(1ULL << c);
            consider(c);
            if (below) consider(63 - __clzll((long long)below));
        }
        if (above) {                        // 2 nearest free above
            int c = __ffsll((long long)above) - 1;
            above &= above - 1;
            consider(c);
            if (above) consider(__ffsll((long long)above) - 1);
        }
        val  = best & ~63ULL;               // (d_bits << 6), row filled by caller
        bpos = bp;
    };

    ull asg   = 0ULL;    // assigned rows (replicated register)
    ull freem = ~0ULL;   // free columns in sorted positions (replicated)

    #pragma unroll 1
    for (int phase = 0; phase < 2; ++phase) {
        const bool inp0 = (phase == 0) ? (a0 > 0.5f) : (a0 <= 0.5f);
        const bool inp1 = (phase == 0) ? (a1 > 0.5f) : (a1 <= 0.5f);

        // Bounded like the reference scan; each productive round assigns >=1.
        #pragma unroll 1
        for (int iter = 0; iter < NSLOT; ++iter) {
            const bool act0 = inp0 && !((asg >> r0) & 1ULL);
            const bool act1 = inp1 && !((asg >> r1) & 1ULL);
            if (__ballot_sync(FULL, act0 || act1) == 0u) break;

            // Both rows evaluated unconditionally (independent chains, ILP);
            // only the atomic is predicated.
            ull v0, v1; int bp0, bp1;
            propose_eval(x0, lowm0, freem, v0, bp0);
            propose_eval(x1, lowm1, freem, v1, bp1);
            // mailbox value: (d desc, row asc); d > 0 so value != 0.
            if (act0) atomicMax(&s_ck[w][bp0], v0 | (ull)(63 - r0));
            if (act1) atomicMax(&s_ck[w][bp1], v1 | (ull)(63 - r1));
            __syncwarp();

            // Accept at owned positions: proposed column takes its best
            // proposer (max d, lowest row) — exactly E = v*A*C mutual-best.
            bool accA = false, accB = false;
            ull  nasg = 0ULL;
            {
                const ull k = s_ck[w][l];
                if (k) {
                    const int r = 63 - (int)(k & 63ULL);
                    s_perm[w][r] = jown_lo;
                    s_ck[w][l]   = 0ULL;
                    nasg |= 1ULL << r;
                    accA = true;
                }
            }
            {
                const ull k = s_ck[w][l + 32];
                if (k) {
                    const int r = 63 - (int)(k & 63ULL);
                    s_perm[w][r]    = jown_hi;
                    s_ck[w][l + 32] = 0ULL;
                    nasg |= 1ULL << r;
                    accB = true;
                }
            }
            // Free-mask update by ballot (bit l == position l / l+32).
            const ull takenNow = (ull)__ballot_sync(FULL, accA)
                               | ((ull)__ballot_sync(FULL, accB) << 32);
            freem &= ~takenNow;
            asg   |= warp_or64(nasg);
            __syncwarp();
        }
    }

    // --- Loss: lane handles rows l, l+32; gather from staged smem ---
    float loss = 0.0f;
    #pragma unroll
    for (int s = 0; s < 2; ++s) {
        const int    r   = s ? r1 : r0;
        const float  a   = s ? a1 : a0;
        const float  x   = s ? x1 : x0;
        const int    pi  = s_perm[w][r];
        const float* ypp = &s_yp[w][pi * FEAT];
        const float* ytr = &s_yt[w][r  * FEAT];

        const float d1 = x - ypp[1];
        const float d0 = a - ypp[0];
        loss += a * 5.0f * d1 * d1
              + a * d0 * d0
              + (1.0f - a) * 0.5f * d0 * d0;
        float s2 = 0.0f;
        #pragma unroll
        for (int f = 2; f < FEAT; ++f) {
            const float d = ytr[f] - ypp[f];
            s2 += d * d;
        }
        loss += a * s2;
    }

    #pragma unroll
    for (int off = 16; off > 0; off >>= 1)
        loss += __shfl_xor_sync(FULL, loss, off);
    if (l == 0) s_wpart[w] = loss;
    __syncthreads();

    if (threadIdx.x == 0) {
        g_blockpart[blockIdx.x] =
            s_wpart[0] + s_wpart[1] + s_wpart[2] + s_wpart[3];
        __threadfence();
        const int c = atomicAdd(&g_count, 1);
        s_flag = (c == GRID - 1);
    }
    __syncthreads();

    if (s_flag) {
        __shared__ float sred[TPB];
        const int t = threadIdx.x;
        float v = 0.0f;
        #pragma unroll
        for (int k = 0; k < GRID / TPB; ++k)
            v += g_blockpart[t + k * TPB];   // fixed order per thread
        sred[t] = v;
        __syncthreads();
        #pragma unroll
        for (int off = TPB / 2; off > 0; off >>= 1) {
            if (t < off) sred[t] += sred[t + off];
            __syncthreads();
        }
        if (t == 0) {
            out[0]  = sred[0];
            g_count = 0;                     // reset for next graph replay
        }
    }
}

extern "C" void kernel_launch(void* const* d_in, const int* in_sizes, int n_in,
                              void* d_out, int out_size)
{
    const float* y_true = (const float*)d_in[0];
    const float* y_pred = (const float*)d_in[1];
    float*       out    = (float*)d_out;

    spotting_kernel<<<GRID, TPB>>>(y_true, y_pred, out);
}

// round 17
// speedup vs baseline: 2.1217x; 2.1217x over previous
#include <cuda_runtime.h>
#include <cuda_bf16.h>

static constexpr int BATCH = 2048;
static constexpr int NSLOT = 64;
static constexpr int FEAT  = 19;
static constexpr int ROWF  = NSLOT * FEAT;       // 1216 floats per tensor/batch
static constexpr int VEC4  = ROWF / 4;           // 304 float4
static constexpr int WPC   = 4;                  // warps (=batches) per CTA
static constexpr int TPB   = 32 * WPC;           // 128
static constexpr int GRID  = BATCH / WPC;        // 512

__device__ float g_blockpart[GRID];
__device__ int   g_count = 0;                    // self-resetting, replay-safe

using ull = unsigned long long;

// Replicated-register 64-bit OR across the warp (2x hardware redux).
__device__ __forceinline__ ull warp_or64(ull v) {
    const unsigned lo = __reduce_or_sync(0xffffffffu, (unsigned)v);
    const unsigned hi = __reduce_or_sync(0xffffffffu, (unsigned)(v >> 32));
    return ((ull)hi << 32) | (ull)lo;
}

// One WARP per batch (R11 structure — 29.2us champion). Sorted nearest-free-
// neighbor matching; tensors staged coalesced in smem; loop state in
// replicated registers. Only change vs R11: lowm hoisted out of the loop.
__global__ __launch_bounds__(TPB) void spotting_kernel(
    const float* __restrict__ y_true,
    const float* __restrict__ y_pred,
    float*       __restrict__ out)
{
    const unsigned FULL = 0xffffffffu;
    const int w = threadIdx.x >> 5;
    const int l = threadIdx.x & 31;
    const int b = blockIdx.x * WPC + w;

    __shared__ alignas(16) float s_yt[WPC][ROWF];
    __shared__ alignas(16) float s_yp[WPC][ROWF];
    __shared__ ull   s_ck[WPC][NSLOT];    // sort keys during setup, then mailbox
    __shared__ ull   s_key[WPC][NSLOT];   // sorted (p_bits<<6)|j
    __shared__ int   s_perm[WPC][NSLOT];  // row -> column
    __shared__ float s_wpart[WPC];
    __shared__ int   s_flag;

    // ---- coalesced stage of this batch (10 x LDG.128 per lane/tensor) ----
    {
        const float4* gt = reinterpret_cast<const float4*>(y_true + (size_t)b * ROWF);
        const float4* gp = reinterpret_cast<const float4*>(y_pred + (size_t)b * ROWF);
        float4* dt = reinterpret_cast<float4*>(s_yt[w]);
        float4* dp = reinterpret_cast<float4*>(s_yp[w]);
        #pragma unroll
        for (int k = l; k < VEC4; k += 32) { dt[k] = gt[k]; dp[k] = gp[k]; }
    }
    __syncwarp();

    const int r0 = l, r1 = l + 32;
    const float a0 = s_yt[w][r0 * FEAT + 0];
    const float x0 = s_yt[w][r0 * FEAT + 1];
    const float a1 = s_yt[w][r1 * FEAT + 0];
    const float x1 = s_yt[w][r1 * FEAT + 1];

    // ---- setup: keys, rank-sort, own-column sorted positions ----
    s_ck[w][r0] = ((ull)__float_as_uint(s_yp[w][r0 * FEAT + 1]) << 6) | (ull)r0;
    s_ck[w][r1] = ((ull)__float_as_uint(s_yp[w][r1 * FEAT + 1]) << 6) | (ull)r1;
    __syncwarp();
    int cpos0, cpos1;
    #pragma unroll
    for (int s = 0; s < 2; ++s) {
        const int c = s ? r1 : r0;
        const ull mykey = s_ck[w][c];
        int rank = 0;
        #pragma unroll 8
        for (int j = 0; j < NSLOT; ++j) rank += (s_ck[w][j] < mykey);
        s_key[w][rank] = mykey;            // unique keys -> perfect scatter
        if (s) cpos1 = rank; else cpos0 = rank;
    }
    __syncwarp();
    s_ck[w][r0] = 0ULL;                    // becomes the proposal mailbox
    s_ck[w][r1] = 0ULL;
    __syncwarp();

    // Binary search: pos = #\{p < x\} over sorted keys (p bits monotone).
    auto lower_pos = [&](float x) -> int {
        const unsigned xb = __float_as_uint(x);
        int pos = 0;
        #pragma unroll
        for (int s = 32; s; s >>= 1) {
            const unsigned pb = (unsigned)(s_key[w][pos + s - 1] >> 6);
            if (pb < xb) pos += s;
        }
        return pos;
    };
    const int pos0 = lower_pos(x0);
    const int pos1 = lower_pos(x1);
    // Hoisted round-invariant below-masks.
    const ull lowm0 = (pos0 >= 64) ? ~0ULL : ((1ULL << pos0) - 1ULL);
    const ull lowm1 = (pos1 >= 64) ? ~0ULL : ((1ULL << pos1) - 1ULL);

    // Candidate eval + proposal: best = max over <=4 nearest-free candidates
    // of (d_bits << 6) | (63 - j) -> max d, lowest j (== jnp.argmax ties;
    // 2 per side covers equal-p pairs and fl(1-m) rounding merges).
    auto propose = [&](float x, ull lowm, int row, ull freem) {
        ull best = 0ULL;
        auto consider = [&](int c) {
            const ull   key = s_key[w][c];
            const float p   = __uint_as_float((unsigned)(key >> 6));
            const int   j   = (int)(key & 63ULL);
            const float d   = 1.0f - fabsf(x - p);
            const ull   sk  = ((ull)__float_as_uint(d) << 6) | (ull)(63 - j);
            if (sk > best) best = sk;
        };
        ull below = freem & lowm;
        ull above = freem & ~lowm;
        if (below) {                        // 2 nearest free below
            int c = 63 - __clzll((long long)below);
            below &= ~(1ULL << c);
            consider(c);
            if (below) consider(63 - __clzll((long long)below));
        }
        if (above) {                        // 2 nearest free above
            int c = __ffsll((long long)above) - 1;
            above &= above - 1;
            consider(c);
            if (above) consider(__ffsll((long long)above) - 1);
        }
        const int jb = 63 - (int)(best & 63ULL);
        // mailbox key: (d desc, row asc); d > 0 so key != 0.
        atomicMax(&s_ck[w][jb], (best & ~63ULL) | (ull)(63 - row));
    };

    ull asg   = 0ULL;    // assigned rows (replicated register)
    ull freem = ~0ULL;   // free columns in sorted positions (replicated)

    #pragma unroll 1
    for (int phase = 0; phase < 2; ++phase) {
        const bool inp0 = (phase == 0) ? (a0 > 0.5f) : (a0 <= 0.5f);
        const bool inp1 = (phase == 0) ? (a1 > 0.5f) : (a1 <= 0.5f);

        // Bounded like the reference scan; each productive round assigns >=1.
        #pragma unroll 1
        for (int iter = 0; iter < NSLOT; ++iter) {
            const bool act0 = inp0 && !((asg >> r0) & 1ULL);
            const bool act1 = inp1 && !((asg >> r1) & 1ULL);
            if (__ballot_sync(FULL, act0 || act1) == 0u) break;

            if (act0) propose(x0, lowm0, r0, freem);
            if (act1) propose(x1, lowm1, r1, freem);
            __syncwarp();

            // Column accept: proposed column takes its best proposer
            // (max d, lowest row) — exactly E = v*A*C mutual-best.
            ull nasg = 0ULL, ntaken = 0ULL;
            #pragma unroll
            for (int s = 0; s < 2; ++s) {
                const int c = s ? r1 : r0;
                const ull k = s_ck[w][c];
                if (k) {
                    const int r = 63 - (int)(k & 63ULL);
                    s_perm[w][r] = c;
                    s_ck[w][c]   = 0ULL;
                    nasg   |= 1ULL << r;
                    ntaken |= 1ULL << (s ? cpos1 : cpos0);
                }
            }
            asg   |= warp_or64(nasg);
            freem &= ~warp_or64(ntaken);
            __syncwarp();
        }
    }

    // --- Loss: lane handles rows l, l+32; gather from staged smem ---
    // (row stride 19 coprime to 32 banks -> conflict-free gather)
    float loss = 0.0f;
    #pragma unroll
    for (int s = 0; s < 2; ++s) {
        const int    r   = s ? r1 : r0;
        const float  a   = s ? a1 : a0;
        const float  x   = s ? x1 : x0;
        const int    pi  = s_perm[w][r];
        const float* ypp = &s_yp[w][pi * FEAT];
        const float* ytr = &s_yt[w][r  * FEAT];

        const float d1 = x - ypp[1];
        const float d0 = a - ypp[0];
        loss += a * 5.0f * d1 * d1
              + a * d0 * d0
              + (1.0f - a) * 0.5f * d0 * d0;
        float s2 = 0.0f;
        #pragma unroll
        for (int f = 2; f < FEAT; ++f) {
            const float d = ytr[f] - ypp[f];
            s2 += d * d;
        }
        loss += a * s2;
    }

    #pragma unroll
    for (int off = 16; off > 0; off >>= 1)
        loss += __shfl_xor_sync(FULL, loss, off);
    if (l == 0) s_wpart[w] = loss;
    __syncthreads();

    if (threadIdx.x == 0) {
        g_blockpart[blockIdx.x] =
            s_wpart[0] + s_wpart[1] + s_wpart[2] + s_wpart[3];
        __threadfence();
        const int c = atomicAdd(&g_count, 1);
        s_flag = (c == GRID - 1);
    }
    __syncthreads();

    if (s_flag) {
        __shared__ float sred[TPB];
        const int t = threadIdx.x;
        float v = 0.0f;
        #pragma unroll
        for (int k = 0; k < GRID / TPB; ++k)
            v += g_blockpart[t + k * TPB];   // fixed order per thread
        sred[t] = v;
        __syncthreads();
        #pragma unroll
        for (int off = TPB / 2; off > 0; off >>= 1) {
            if (t < off) sred[t] += sred[t + off];
            __syncthreads();
        }
        if (t == 0) {
            out[0]  = sred[0];
            g_count = 0;                     // reset for next graph replay
        }
    }
}

extern "C" void kernel_launch(void* const* d_in, const int* in_sizes, int n_in,
                              void* d_out, int out_size)
{
    const float* y_true = (const float*)d_in[0];
    const float* y_pred = (const float*)d_in[1];
    float*       out    = (float*)d_out;

    spotting_kernel<<<GRID, TPB>>>(y_true, y_pred, out);
}